// round 10
// baseline (speedup 1.0000x reference)
#include <cuda_runtime.h>
#include <cstdint>

// Problem constants (fixed by the reference: N=16, C=4, H=W=768)
#define NB   16
#define NC   4
#define MPIX (768 * 768)        // 589824 pixels per batch image
#define NG4  (MPIX / 4)         // 147456 float4-groups per class row
#define GB   24                 // blocks per image -> 384 blocks total
#define NT   256                // threads per block
#define ITERS 24                // 147456 / (24*256) == 24 exactly
#define STRIDE (GB * NT)        // 6144
#define TOTAL_BLOCKS (GB * NB)  // 384
#define STAGES 3
#define STAGE_BYTES (6 * NT * 16)              // 24576
#define SMEM_DYN (STAGES * STAGE_BYTES)        // 73728

__device__ float g_scratch[NB * 8 * GB];
__device__ unsigned int g_count = 0;

using u64 = unsigned long long;

// ---------------------------------------------------------------------------
// Packed f32x2 primitives (FFMA2/FADD2/FMUL2 via PTX .f32x2)
// ---------------------------------------------------------------------------
__device__ __forceinline__ u64 pk2(float lo, float hi) {
    u64 r; asm("mov.b64 %0, {%1, %2};" : "=l"(r) : "f"(lo), "f"(hi)); return r;
}
__device__ __forceinline__ void upk2(float& lo, float& hi, u64 v) {
    asm("mov.b64 {%0, %1}, %2;" : "=f"(lo), "=f"(hi) : "l"(v));
}
__device__ __forceinline__ u64 f2fma(u64 a, u64 b, u64 c) {
    u64 d; asm("fma.rn.f32x2 %0, %1, %2, %3;" : "=l"(d) : "l"(a), "l"(b), "l"(c)); return d;
}
__device__ __forceinline__ u64 f2mul(u64 a, u64 b) {
    u64 d; asm("mul.rn.f32x2 %0, %1, %2;" : "=l"(d) : "l"(a), "l"(b)); return d;
}
__device__ __forceinline__ u64 f2add(u64 a, u64 b) {
    u64 d; asm("add.rn.f32x2 %0, %1, %2;" : "=l"(d) : "l"(a), "l"(b)); return d;
}

struct PkConsts { u64 L2E, MAGIC, NEG1, C3, C2, C1, C0, TWO; };

// Packed exp: identical per-element arithmetic to R8/R9.
__device__ __forceinline__ u64 fexp2p(u64 x, const PkConsts& K) {
    u64 y = f2mul(x, K.L2E);
    u64 t = f2add(y, K.MAGIC);
    u64 d = f2fma(K.MAGIC, K.NEG1, t);    // t - MAGIC = k (exact)
    u64 f = f2fma(d, K.NEG1, y);          // y - k in [-0.5, 0.5]
    u64 p = f2fma(K.C3, f, K.C2);
    p = f2fma(p, f, K.C1);
    p = f2fma(p, f, K.C0);
    float tl, th, pl, ph;
    upk2(tl, th, t);
    upk2(pl, ph, p);
    int el = __float_as_int(pl) + (__float_as_int(tl) << 23);
    int eh = __float_as_int(ph) + (__float_as_int(th) << 23);
    return pk2(__int_as_float(el), __int_as_float(eh));
}

__device__ __forceinline__ u64 frcp2p(u64 s, const PkConsts& K) {
    float sl, sh;
    upk2(sl, sh, s);
    float rl = __int_as_float(0x7EF311C3 - __float_as_int(sl));
    float rh = __int_as_float(0x7EF311C3 - __float_as_int(sh));
    u64 r  = pk2(rl, rh);
    u64 ns = f2mul(s, K.NEG1);
    r = f2mul(r, f2fma(ns, r, K.TWO));
    r = f2mul(r, f2fma(ns, r, K.TWO));
    return r;
}

__device__ __forceinline__ void pair_accum(
    u64 v0, u64 v1, u64 v2, u64 v3,
    int t0, int t1, int m0, int m1,
    u64 num2[NC], u64 den2[NC], const PkConsts& K)
{
    u64 e[NC];
    e[0] = fexp2p(v0, K);
    e[1] = fexp2p(v1, K);
    e[2] = fexp2p(v2, K);
    e[3] = fexp2p(v3, K);
    u64 S = f2add(f2add(e[0], e[1]), f2add(e[2], e[3]));
    u64 r = frcp2p(S, K);

    u64 wf = pk2((float)m0, (float)m1);
    u64 u  = f2mul(wf, r);
    u64 q  = f2mul(u, r);
    u64 a  = f2fma(wf, K.NEG1, K.TWO);    // 2 - wf
    u64 b  = f2add(a, K.NEG1);            // 1 - wf

    #pragma unroll
    for (int c = 0; c < NC; c++) {
        u64 eq = pk2((t0 == c) ? 1.0f : 0.0f, (t1 == c) ? 1.0f : 0.0f);
        den2[c] = f2fma(q, f2mul(e[c], e[c]), den2[c]);
        den2[c] = f2fma(eq, a, den2[c]);
        num2[c] = f2fma(eq, f2fma(u, e[c], b), num2[c]);
    }
}

// ---------------------------------------------------------------------------
// cp.async helpers (per-thread groups; thread-private data, no block sync)
// ---------------------------------------------------------------------------
__device__ __forceinline__ void cpa16(uint32_t dst_smem, const void* src) {
    asm volatile("cp.async.cg.shared.global [%0], [%1], 16;"
                 :: "r"(dst_smem), "l"(src) : "memory");
}
__device__ __forceinline__ void cpa_commit() {
    asm volatile("cp.async.commit_group;" ::: "memory");
}
template <int N>
__device__ __forceinline__ void cpa_wait() {
    asm volatile("cp.async.wait_group %0;" :: "n"(N) : "memory");
}

// SoA stage layout: stream j (0..3 pred classes, 4 tgt, 5 msk), thread t:
//   offset = ((s*6 + j)*NT + t) * 16   -> warp LDS.128 at 16B stride, conflict-free
__device__ __forceinline__ void fill_stage(
    uint32_t smem_base, int s, int tid, int g,
    const float4* p4, const int4* t4, const int4* m4)
{
    uint32_t base = smem_base + (uint32_t)(((s * 6) * NT + tid) * 16);
    cpa16(base + 0 * (NT * 16), p4 + g);
    cpa16(base + 1 * (NT * 16), p4 + g + NG4);
    cpa16(base + 2 * (NT * 16), p4 + g + 2 * NG4);
    cpa16(base + 3 * (NT * 16), p4 + g + 3 * NG4);
    cpa16(base + 4 * (NT * 16), t4 + g);
    cpa16(base + 5 * (NT * 16), m4 + g);
    cpa_commit();
}

__device__ __forceinline__ void consume_stage(
    const char* smem, int s, int tid,
    u64 num2[NC], u64 den2[NC], const PkConsts& K)
{
    const char* sp = smem + ((size_t)((s * 6) * NT + tid) * 16);
    float4 x0 = *reinterpret_cast<const float4*>(sp + 0 * (NT * 16));
    float4 x1 = *reinterpret_cast<const float4*>(sp + 1 * (NT * 16));
    float4 x2 = *reinterpret_cast<const float4*>(sp + 2 * (NT * 16));
    float4 x3 = *reinterpret_cast<const float4*>(sp + 3 * (NT * 16));
    int4   tt = *reinterpret_cast<const int4*>(sp + 4 * (NT * 16));
    int4   mm = *reinterpret_cast<const int4*>(sp + 5 * (NT * 16));

    pair_accum(pk2(x0.x, x0.y), pk2(x1.x, x1.y), pk2(x2.x, x2.y), pk2(x3.x, x3.y),
               tt.x, tt.y, mm.x, mm.y, num2, den2, K);
    pair_accum(pk2(x0.z, x0.w), pk2(x1.z, x1.w), pk2(x2.z, x2.w), pk2(x3.z, x3.w),
               tt.z, tt.w, mm.z, mm.w, num2, den2, K);
}

__global__ void __launch_bounds__(NT, 3)
dice_fused(const float* __restrict__ pred,
           const int*   __restrict__ tgt,
           const int*   __restrict__ msk,
           float*       __restrict__ out) {
    extern __shared__ char smem[];
    const int n   = blockIdx.y;
    const int tid = threadIdx.x;

    const float4* p4 = reinterpret_cast<const float4*>(pred + (size_t)n * NC * MPIX);
    const int4*   t4 = reinterpret_cast<const int4*>(tgt  + (size_t)n * MPIX);
    const int4*   m4 = reinterpret_cast<const int4*>(msk  + (size_t)n * MPIX);

    uint32_t smem_u32 = (uint32_t)__cvta_generic_to_shared(smem);

    PkConsts K;
    K.L2E   = pk2(1.442695041f, 1.442695041f);
    K.MAGIC = pk2(12582912.0f, 12582912.0f);
    K.NEG1  = pk2(-1.0f, -1.0f);
    K.C3    = pk2(0.0559207f, 0.0559207f);
    K.C2    = pk2(0.2426310f, 0.2426310f);
    K.C1    = pk2(0.6931210f, 0.6931210f);
    K.C0    = pk2(0.9999250f, 0.9999250f);
    K.TWO   = pk2(2.0f, 2.0f);

    u64 num2[NC] = {0ull, 0ull, 0ull, 0ull};
    u64 den2[NC] = {0ull, 0ull, 0ull, 0ull};

    const int g0 = blockIdx.x * NT + tid;   // iteration i reads g0 + i*STRIDE

    // ---- prologue: fill all STAGES ----
    fill_stage(smem_u32, 0, tid, g0 + 0 * STRIDE, p4, t4, m4);
    fill_stage(smem_u32, 1, tid, g0 + 1 * STRIDE, p4, t4, m4);
    fill_stage(smem_u32, 2, tid, g0 + 2 * STRIDE, p4, t4, m4);

    // ---- main pipeline: consume stage it%3, refill with it+3 ----
    #pragma unroll 1
    for (int it = 0; it < ITERS - STAGES; it++) {
        cpa_wait<STAGES - 1>();            // oldest group (== iter it) complete
        int s = it % STAGES;
        consume_stage(smem, s, tid, num2, den2, K);
        fill_stage(smem_u32, s, tid, g0 + (it + STAGES) * STRIDE, p4, t4, m4);
    }
    // ---- tail: drain last 3 stages ----
    cpa_wait<2>(); consume_stage(smem, (ITERS - 3) % STAGES, tid, num2, den2, K);
    cpa_wait<1>(); consume_stage(smem, (ITERS - 2) % STAGES, tid, num2, den2, K);
    cpa_wait<0>(); consume_stage(smem, (ITERS - 1) % STAGES, tid, num2, den2, K);

    // Collapse packed halves -> scalar per-class partials
    float num[NC], den[NC];
    #pragma unroll
    for (int c = 0; c < NC; c++) {
        float l, h;
        upk2(l, h, num2[c]); num[c] = l + h;
        upk2(l, h, den2[c]); den[c] = l + h;
    }

    // ---- block reduction ----
    #pragma unroll
    for (int c = 0; c < NC; c++) {
        #pragma unroll
        for (int off = 16; off > 0; off >>= 1) {
            num[c] += __shfl_down_sync(0xffffffffu, num[c], off);
            den[c] += __shfl_down_sync(0xffffffffu, den[c], off);
        }
    }

    __shared__ float sh[8][NT / 32];
    const int lane = tid & 31;
    const int wrp  = tid >> 5;
    if (lane == 0) {
        #pragma unroll
        for (int c = 0; c < NC; c++) {
            sh[c * 2 + 0][wrp] = num[c];
            sh[c * 2 + 1][wrp] = den[c];
        }
    }
    __syncthreads();

    if (tid < 8) {
        float s = 0.f;
        #pragma unroll
        for (int w = 0; w < NT / 32; w++) s += sh[tid][w];
        g_scratch[(n * 8 + tid) * GB + blockIdx.x] = s;
    }

    // ---- last-block-done final reduction ----
    __shared__ unsigned int s_is_last;
    __threadfence();
    if (tid == 0) {
        unsigned int prev = atomicAdd(&g_count, 1u);
        s_is_last = (prev == TOTAL_BLOCKS - 1) ? 1u : 0u;
    }
    __syncthreads();
    if (!s_is_last) return;
    __threadfence();

    __shared__ float sums[NB * 8];
    __shared__ float loss[NB * NC];
    const int t = tid;

    if (t < NB * 8) {
        float s = 0.f;
        const float* p = g_scratch + t * GB;
        #pragma unroll 8
        for (int b = 0; b < GB; b++) s += p[b];
        sums[t] = s;
    }
    __syncthreads();

    if (t < NB * NC) {
        int nn = t / NC, c = t % NC;
        float nu = sums[nn * 8 + c * 2 + 0] + 1.0f;   // + SMOOTH
        float de = sums[nn * 8 + c * 2 + 1] + 1.0f;   // + SMOOTH
        loss[t] = 1.0f - nu / de;
    }
    __syncthreads();

    if (t == 0) {
        float s = 0.f;
        #pragma unroll
        for (int i = 0; i < NB * NC; i++) s += loss[i];
        out[0] = s / (float)(NB * NC);
        g_count = 0;
    }
}

extern "C" void kernel_launch(void* const* d_in, const int* in_sizes, int n_in,
                              void* d_out, int out_size) {
    const float* pred = (const float*)d_in[0];
    const int*   tgt  = (const int*)d_in[1];
    const int*   msk  = (const int*)d_in[2];
    float*       out  = (float*)d_out;

    // Idempotent; executes immediately (not a stream op) — capture-safe.
    cudaFuncSetAttribute(dice_fused, cudaFuncAttributeMaxDynamicSharedMemorySize, SMEM_DYN);

    dim3 grid(GB, NB);
    dice_fused<<<grid, NT, SMEM_DYN>>>(pred, tgt, msk, out);
}

// round 11
// speedup vs baseline: 1.2340x; 1.2340x over previous
#include <cuda_runtime.h>
#include <cstdint>

// Problem constants (fixed by the reference: N=16, C=4, H=W=768)
#define NB   16
#define NC   4
#define MPIX (768 * 768)        // 589824 pixels per batch image
#define NG4  (MPIX / 4)         // 147456 float4-groups per class row
#define GB   18                 // blocks per image -> 288 blocks (1 wave @2/SM)
#define NT   256                // threads per block
#define ITERS 32                // 147456 / (18*256) == 32 exactly (even)
#define STRIDE (GB * NT)        // 4608
#define TOTAL_BLOCKS (GB * NB)  // 288

__device__ float g_scratch[NB * 8 * GB];
__device__ unsigned int g_count = 0;

using u64 = unsigned long long;

// ---------------------------------------------------------------------------
// Packed f32x2 primitives (FFMA2/FADD2/FMUL2 via PTX .f32x2)
// ---------------------------------------------------------------------------
__device__ __forceinline__ u64 pk2(float lo, float hi) {
    u64 r; asm("mov.b64 %0, {%1, %2};" : "=l"(r) : "f"(lo), "f"(hi)); return r;
}
__device__ __forceinline__ void upk2(float& lo, float& hi, u64 v) {
    asm("mov.b64 {%0, %1}, %2;" : "=f"(lo), "=f"(hi) : "l"(v));
}
__device__ __forceinline__ u64 f2fma(u64 a, u64 b, u64 c) {
    u64 d; asm("fma.rn.f32x2 %0, %1, %2, %3;" : "=l"(d) : "l"(a), "l"(b), "l"(c)); return d;
}
__device__ __forceinline__ u64 f2mul(u64 a, u64 b) {
    u64 d; asm("mul.rn.f32x2 %0, %1, %2;" : "=l"(d) : "l"(a), "l"(b)); return d;
}
__device__ __forceinline__ u64 f2add(u64 a, u64 b) {
    u64 d; asm("add.rn.f32x2 %0, %1, %2;" : "=l"(d) : "l"(a), "l"(b)); return d;
}

struct PkConsts { u64 L2E, MAGIC, NEG1, C3, C2, C1, C0, TWO; };

// Packed exp: identical per-element arithmetic to R8/R9 (rel_err preserved).
__device__ __forceinline__ u64 fexp2p(u64 x, const PkConsts& K) {
    u64 y = f2mul(x, K.L2E);
    u64 t = f2add(y, K.MAGIC);
    u64 d = f2fma(K.MAGIC, K.NEG1, t);    // t - MAGIC = k (exact)
    u64 f = f2fma(d, K.NEG1, y);          // y - k in [-0.5, 0.5]
    u64 p = f2fma(K.C3, f, K.C2);
    p = f2fma(p, f, K.C1);
    p = f2fma(p, f, K.C0);
    float tl, th, pl, ph;
    upk2(tl, th, t);
    upk2(pl, ph, p);
    int el = __float_as_int(pl) + (__float_as_int(tl) << 23);
    int eh = __float_as_int(ph) + (__float_as_int(th) << 23);
    return pk2(__int_as_float(el), __int_as_float(eh));
}

__device__ __forceinline__ u64 frcp2p(u64 s, const PkConsts& K) {
    float sl, sh;
    upk2(sl, sh, s);
    float rl = __int_as_float(0x7EF311C3 - __float_as_int(sl));
    float rh = __int_as_float(0x7EF311C3 - __float_as_int(sh));
    u64 r  = pk2(rl, rh);
    u64 ns = f2mul(s, K.NEG1);
    r = f2mul(r, f2fma(ns, r, K.TWO));
    r = f2mul(r, f2fma(ns, r, K.TWO));
    return r;
}

__device__ __forceinline__ void pair_accum(
    u64 v0, u64 v1, u64 v2, u64 v3,
    int t0, int t1, int m0, int m1,
    u64 num2[NC], u64 den2[NC], const PkConsts& K)
{
    u64 e[NC];
    e[0] = fexp2p(v0, K);
    e[1] = fexp2p(v1, K);
    e[2] = fexp2p(v2, K);
    e[3] = fexp2p(v3, K);
    u64 S = f2add(f2add(e[0], e[1]), f2add(e[2], e[3]));
    u64 r = frcp2p(S, K);

    u64 wf = pk2((float)m0, (float)m1);
    u64 u  = f2mul(wf, r);
    u64 q  = f2mul(u, r);
    u64 a  = f2fma(wf, K.NEG1, K.TWO);    // 2 - wf
    u64 b  = f2add(a, K.NEG1);            // 1 - wf

    #pragma unroll
    for (int c = 0; c < NC; c++) {
        u64 eq = pk2((t0 == c) ? 1.0f : 0.0f, (t1 == c) ? 1.0f : 0.0f);
        den2[c] = f2fma(q, f2mul(e[c], e[c]), den2[c]);
        den2[c] = f2fma(eq, a, den2[c]);
        num2[c] = f2fma(eq, f2fma(u, e[c], b), num2[c]);
    }
}

// One iteration's data: 4 pred float4 + tgt int4 + msk int4 (24 regs).
struct Buf { float4 x0, x1, x2, x3; int4 tt, mm; };

__device__ __forceinline__ void load_buf(
    Buf& b, int g, const float4* p4, const int4* t4, const int4* m4)
{
    // Streaming loads: zero reuse -> evict-first.
    b.x0 = __ldcs(p4 + g);
    b.x1 = __ldcs(p4 + g + NG4);
    b.x2 = __ldcs(p4 + g + 2 * NG4);
    b.x3 = __ldcs(p4 + g + 3 * NG4);
    b.tt = __ldcs(t4 + g);
    b.mm = __ldcs(m4 + g);
}

__device__ __forceinline__ void consume_buf(
    const Buf& b, u64 num2[NC], u64 den2[NC], const PkConsts& K)
{
    pair_accum(pk2(b.x0.x, b.x0.y), pk2(b.x1.x, b.x1.y),
               pk2(b.x2.x, b.x2.y), pk2(b.x3.x, b.x3.y),
               b.tt.x, b.tt.y, b.mm.x, b.mm.y, num2, den2, K);
    pair_accum(pk2(b.x0.z, b.x0.w), pk2(b.x1.z, b.x1.w),
               pk2(b.x2.z, b.x2.w), pk2(b.x3.z, b.x3.w),
               b.tt.z, b.tt.w, b.mm.z, b.mm.w, num2, den2, K);
}

__global__ void __launch_bounds__(NT, 2)
dice_fused(const float* __restrict__ pred,
           const int*   __restrict__ tgt,
           const int*   __restrict__ msk,
           float*       __restrict__ out) {
    const int n   = blockIdx.y;
    const int tid = threadIdx.x;

    const float4* p4 = reinterpret_cast<const float4*>(pred + (size_t)n * NC * MPIX);
    const int4*   t4 = reinterpret_cast<const int4*>(tgt  + (size_t)n * MPIX);
    const int4*   m4 = reinterpret_cast<const int4*>(msk  + (size_t)n * MPIX);

    PkConsts K;
    K.L2E   = pk2(1.442695041f, 1.442695041f);
    K.MAGIC = pk2(12582912.0f, 12582912.0f);
    K.NEG1  = pk2(-1.0f, -1.0f);
    K.C3    = pk2(0.0559207f, 0.0559207f);
    K.C2    = pk2(0.2426310f, 0.2426310f);
    K.C1    = pk2(0.6931210f, 0.6931210f);
    K.C0    = pk2(0.9999250f, 0.9999250f);
    K.TWO   = pk2(2.0f, 2.0f);

    u64 num2[NC] = {0ull, 0ull, 0ull, 0ull};
    u64 den2[NC] = {0ull, 0ull, 0ull, 0ull};

    const int g0 = blockIdx.x * NT + tid;

    // ---- software pipeline: double-buffer prefetch in registers ----
    Buf A, B;
    load_buf(A, g0, p4, t4, m4);

    #pragma unroll 1
    for (int it = 0; it < ITERS; it += 2) {
        // prefetch B for it+1 (always valid: it+1 <= ITERS-1), overlap with compute(A)
        load_buf(B, g0 + (it + 1) * STRIDE, p4, t4, m4);
        consume_buf(A, num2, den2, K);
        // prefetch A for it+2 (guarded on last iteration), overlap with compute(B)
        if (it + 2 < ITERS)
            load_buf(A, g0 + (it + 2) * STRIDE, p4, t4, m4);
        consume_buf(B, num2, den2, K);
    }

    // Collapse packed halves -> scalar per-class partials
    float num[NC], den[NC];
    #pragma unroll
    for (int c = 0; c < NC; c++) {
        float l, h;
        upk2(l, h, num2[c]); num[c] = l + h;
        upk2(l, h, den2[c]); den[c] = l + h;
    }

    // ---- block reduction ----
    #pragma unroll
    for (int c = 0; c < NC; c++) {
        #pragma unroll
        for (int off = 16; off > 0; off >>= 1) {
            num[c] += __shfl_down_sync(0xffffffffu, num[c], off);
            den[c] += __shfl_down_sync(0xffffffffu, den[c], off);
        }
    }

    __shared__ float sh[8][NT / 32];
    const int lane = tid & 31;
    const int wrp  = tid >> 5;
    if (lane == 0) {
        #pragma unroll
        for (int c = 0; c < NC; c++) {
            sh[c * 2 + 0][wrp] = num[c];
            sh[c * 2 + 1][wrp] = den[c];
        }
    }
    __syncthreads();

    if (tid < 8) {
        float s = 0.f;
        #pragma unroll
        for (int w = 0; w < NT / 32; w++) s += sh[tid][w];
        g_scratch[(n * 8 + tid) * GB + blockIdx.x] = s;
    }

    // ---- last-block-done final reduction (fixed order, deterministic) ----
    __shared__ unsigned int s_is_last;
    __threadfence();
    if (tid == 0) {
        unsigned int prev = atomicAdd(&g_count, 1u);
        s_is_last = (prev == TOTAL_BLOCKS - 1) ? 1u : 0u;
    }
    __syncthreads();
    if (!s_is_last) return;
    __threadfence();

    __shared__ float sums[NB * 8];
    __shared__ float loss[NB * NC];
    const int t = tid;

    if (t < NB * 8) {
        float s = 0.f;
        const float* p = g_scratch + t * GB;
        #pragma unroll 6
        for (int b = 0; b < GB; b++) s += p[b];
        sums[t] = s;
    }
    __syncthreads();

    if (t < NB * NC) {
        int nn = t / NC, c = t % NC;
        float nu = sums[nn * 8 + c * 2 + 0] + 1.0f;   // + SMOOTH
        float de = sums[nn * 8 + c * 2 + 1] + 1.0f;   // + SMOOTH
        loss[t] = 1.0f - nu / de;
    }
    __syncthreads();

    if (t == 0) {
        float s = 0.f;
        #pragma unroll
        for (int i = 0; i < NB * NC; i++) s += loss[i];
        out[0] = s / (float)(NB * NC);      // mean over batch, sum / C
        g_count = 0;                        // reset for next graph replay
    }
}

extern "C" void kernel_launch(void* const* d_in, const int* in_sizes, int n_in,
                              void* d_out, int out_size) {
    const float* pred = (const float*)d_in[0];
    const int*   tgt  = (const int*)d_in[1];
    const int*   msk  = (const int*)d_in[2];
    float*       out  = (float*)d_out;

    dim3 grid(GB, NB);
    dice_fused<<<grid, NT>>>(pred, tgt, msk, out);
}